// round 8
// baseline (speedup 1.0000x reference)
#include <cuda_runtime.h>
#include <math.h>

#define NB 4096
#define NC 256
#define ROWS 4
#define NBQ (NB / ROWS)   // 1024

// Per-circuit constants, SoA float4 layout (coalesced per-warp loads):
// g_cw0[c] = w0 angles (q0..q3)
// g_cA[c]  = A0,B0,E0,F0
// g_cB[c]  = A1,B1,A2,B2
// g_cC[c]  = A3,B3,E3,F3
__device__ float4 g_cw0[NC];
__device__ float4 g_cA[NC];
__device__ float4 g_cB[NC];
__device__ float4 g_cC[NC];

// ---- Exact 4-qubit sim (verified R1 path), parameterized by half-angle trig ----
__device__ void sim_probe(const float ch[4], const float sh[4],
                          const float g1c[4], const float g1s[4], float o[4]) {
    float f0[2] = {ch[0], sh[0]};
    float f1[2] = {ch[1], sh[1]};
    float f2[2] = {ch[2], sh[2]};
    float f3[2] = {ch[3], sh[3]};
    float m2[4], m3[8], m4[16];
    for (int i = 0; i < 2; ++i)
        for (int j = 0; j < 2; ++j) m2[i * 2 + j] = f0[i] * f1[j];
    for (int i = 0; i < 4; ++i)
        for (int j = 0; j < 2; ++j) m3[i * 2 + j] = m2[i] * f2[j];
    for (int i = 0; i < 8; ++i)
        for (int j = 0; j < 2; ++j) m4[i * 2 + j] = m3[i] * f3[j];

    float su[16];
    for (int x = 0; x < 16; ++x) {
        const int b0 = (x >> 3) & 1, b1 = (x >> 2) & 1, b2 = (x >> 1) & 1, b3 = x & 1;
        const int y = (b1 ^ b2 ^ b3) * 8 + (b0 ^ b1) * 4 + (b0 ^ b1 ^ b2) * 2 + (b0 ^ b1 ^ b2 ^ b3);
        const int pcnt = b0 + b1 + b2 + b3;
        su[y] = ((pcnt >> 1) & 1) ? -m4[x] : m4[x];
    }
    {   // q3 RX (real Givens)
        const float cg = g1c[3], sg = g1s[3];
        for (int yy = 0; yy < 16; yy += 2) {
            const float v0 = su[yy], v1 = su[yy + 1];
            su[yy] = cg * v0 - sg * v1;
            su[yy + 1] = sg * v0 + cg * v1;
        }
    }
    float re[16], im[16];
    {   // q2 RX (sparse complexification)
        const float cg = g1c[2], sg = g1s[2];
        for (int hi = 0; hi < 16; hi += 4) {
            int i0 = hi, i1 = hi + 2;
            re[i0] = cg * su[i0];   im[i0] = -sg * su[i1];
            re[i1] = cg * su[i1];   im[i1] = -sg * su[i0];
            i0 = hi + 1; i1 = hi + 3;
            re[i0] = -sg * su[i1];  im[i0] = -cg * su[i0];
            re[i1] = -sg * su[i0];  im[i1] = -cg * su[i1];
        }
    }
    {   // q1 RX
        const float cg = g1c[1], sg = g1s[1];
        for (int hi = 0; hi < 16; hi += 8)
            for (int lo = 0; lo < 4; ++lo) {
                const int i0 = hi + lo, i1 = i0 + 4;
                const float r0 = re[i0], iv0 = im[i0], r1 = re[i1], iv1 = im[i1];
                re[i0] = cg * r0 + sg * iv1;
                im[i0] = cg * iv0 - sg * r1;
                re[i1] = cg * r1 + sg * iv0;
                im[i1] = cg * iv1 - sg * r0;
            }
    }
    {   // q0 RX
        const float cg = g1c[0], sg = g1s[0];
        for (int lo = 0; lo < 8; ++lo) {
            const int i0 = lo, i1 = lo + 8;
            const float r0 = re[i0], iv0 = im[i0], r1 = re[i1], iv1 = im[i1];
            re[i0] = cg * r0 + sg * iv1;
            im[i0] = cg * iv0 - sg * r1;
            re[i1] = cg * r1 + sg * iv0;
            im[i1] = cg * iv1 - sg * r0;
        }
    }
    float S[8], D[8];
    for (int j = 0; j < 8; ++j) {
        const int ya = 2 * j, yb = 2 * j + 1;
        const float pa = re[ya] * re[ya] + im[ya] * im[ya];
        const float pb = re[yb] * re[yb] + im[yb] * im[yb];
        S[j] = pa + pb;
        D[j] = pa - pb;
    }
    float o0 = 0.f, o1 = 0.f, o2 = 0.f, o3 = 0.f;
    for (int j = 0; j < 8; ++j) {
        const int z0 = (j >> 2) & 1, z1 = (j >> 1) & 1, z2 = j & 1;
        o0 += ((z1 ^ z2) ? -D[j] : D[j]);
        o1 += ((z0 ^ z1) ? -S[j] : S[j]);
        o2 += ((z0 ^ z1 ^ z2) ? -S[j] : S[j]);
        o3 += ((z0 ^ z1 ^ z2) ? -D[j] : D[j]);
    }
    o[0] = o0; o[1] = o1; o[2] = o2; o[3] = o3;
}

// Prep: 24 blocks x 64 threads; thread -> (probe p, circuit c).
// Probe masks (bit q -> Theta_q = pi/2):
//   p0=0x0 -> A0,A1,A2,A3   p1=0xB -> B0       p2=0xA -> E0,B2
//   p3=0x1 -> F0,F3         p4=0x5 -> B1,B3    p5=0x4 -> E3
__global__ void prep_kernel(const float* __restrict__ w) {
    const int gt = blockIdx.x * 64 + threadIdx.x;   // 0..1535
    const int p = gt >> 8;                          // 0..5
    const int c = gt & 255;                         // 0..255

    float g1c[4], g1s[4];
#pragma unroll
    for (int q = 0; q < 4; ++q) {
        const float a = 0.5f * w[c * 8 + 4 + q];    // half angle w1, in [0, pi)
        g1s[q] = __sinf(a);
        g1c[q] = __cosf(a);
    }

    const int pm[6] = {0x0, 0xB, 0xA, 0x1, 0x5, 0x4};
    const float R = 0.70710678118654752f;
    float ch[4], sh[4];
#pragma unroll
    for (int q = 0; q < 4; ++q) {
        const bool hot = (pm[p] >> q) & 1;
        ch[q] = hot ? R : 1.0f;
        sh[q] = hot ? R : 0.0f;
    }
    float O[4];
    sim_probe(ch, sh, g1c, g1s, O);

    float* A = reinterpret_cast<float*>(g_cA) + c * 4;
    float* Bp = reinterpret_cast<float*>(g_cB) + c * 4;
    float* Cp = reinterpret_cast<float*>(g_cC) + c * 4;
    switch (p) {
        case 0: {
            float4 w0;
            w0.x = w[c * 8 + 0]; w0.y = w[c * 8 + 1];
            w0.z = w[c * 8 + 2]; w0.w = w[c * 8 + 3];
            g_cw0[c] = w0;
            A[0]  = O[0];   // A0
            Bp[0] = O[1];   // A1
            Bp[2] = O[2];   // A2
            Cp[0] = O[3];   // A3
            break;
        }
        case 1: A[1]  = O[0]; break;               // B0
        case 2: A[2]  = O[0]; Bp[3] = O[2]; break; // E0, B2
        case 3: A[3]  = O[0]; Cp[3] = O[3]; break; // F0, F3
        case 4: Bp[1] = O[1]; Cp[1] = O[3]; break; // B1, B3
        case 5: Cp[2] = O[3]; break;               // E3
    }
}

// One full Heisenberg evaluation from an x-vector and register-resident coefs.
__device__ __forceinline__ float4 eval_sim(const float4 xv, const float4 kw,
                                           const float4 k2, const float4 k3,
                                           const float4 k4) {
    const float t0 = xv.x + kw.x;
    const float t1 = xv.y + kw.y;
    const float t2 = xv.z + kw.z;
    const float t3 = xv.w + kw.w;
    const float S0 = __sinf(t0), C0 = __cosf(t0);
    const float S1 = __sinf(t1), C1 = __cosf(t1);
    const float S2 = __sinf(t2), C2 = __cosf(t2);
    const float S3 = __sinf(t3), C3 = __cosf(t3);

    const float C1C3 = C1 * C3;
    const float S1S3 = S1 * S3;
    const float C0C2 = C0 * C2;
    const float S0S2 = S0 * S2;
    const float C0S2 = C0 * S2;
    const float S0C2 = S0 * C2;

    float o0 = k2.x * (C0 * C1C3);
    o0 = fmaf(k2.y, S0 * S1S3, o0);
    o0 = fmaf(k2.z, C0 * S1S3, o0);
    o0 = fmaf(k2.w, S0 * C1C3, o0);

    float o1 = k3.x * (C0C2 * C3);
    o1 = fmaf(k3.y, S0S2 * C3, o1);

    const float o2 = fmaf(k3.z, C1C3, k3.w * S1S3);

    float o3 = k4.x * C0C2;
    o3 = fmaf(k4.y, S0S2, o3);
    o3 = fmaf(k4.z, C0S2, o3);
    o3 = fmaf(k4.w, S0C2, o3);

    float4 o;
    o.x = o0; o.y = o1; o.z = o2; o.w = o3;
    return o;
}

__global__ void __launch_bounds__(256)
qsim7_kernel(const float4* __restrict__ x4, float4* __restrict__ out4) {
    const int b = blockIdx.x;          // 0..1023
    const int c = threadIdx.x;

    // Batch all independent loads first (MLP).
    const float4 xv0 = x4[(b + 0 * NBQ) * NC + c];
    const float4 xv1 = x4[(b + 1 * NBQ) * NC + c];
    const float4 xv2 = x4[(b + 2 * NBQ) * NC + c];
    const float4 xv3 = x4[(b + 3 * NBQ) * NC + c];
    const float4 kw = g_cw0[c];
    const float4 k2 = g_cA[c];
    const float4 k3 = g_cB[c];
    const float4 k4 = g_cC[c];

    const float4 o0 = eval_sim(xv0, kw, k2, k3, k4);
    const float4 o1 = eval_sim(xv1, kw, k2, k3, k4);
    const float4 o2 = eval_sim(xv2, kw, k2, k3, k4);
    const float4 o3 = eval_sim(xv3, kw, k2, k3, k4);

    out4[(b + 0 * NBQ) * NC + c] = o0;
    out4[(b + 1 * NBQ) * NC + c] = o1;
    out4[(b + 2 * NBQ) * NC + c] = o2;
    out4[(b + 3 * NBQ) * NC + c] = o3;
}

extern "C" void kernel_launch(void* const* d_in, const int* in_sizes, int n_in,
                              void* d_out, int out_size) {
    const float* x = (const float*)d_in[0];        // (4096, 1024)
    const float* w = (const float*)d_in[1];        // (256, 2, 4)
    float* out = (float*)d_out;                    // (4096, 1024)

    prep_kernel<<<24, 64>>>(w);
    qsim7_kernel<<<NBQ, 256>>>(reinterpret_cast<const float4*>(x),
                               reinterpret_cast<float4*>(out));
}

// round 9
// speedup vs baseline: 1.2043x; 1.2043x over previous
#include <cuda_runtime.h>
#include <math.h>

#define NB 4096
#define NC 256
#define ROWS 4
#define NBQ (NB / ROWS)   // 1024

// One full Heisenberg evaluation from an x-vector and register-resident coefs.
__device__ __forceinline__ float4 eval_sim(const float4 xv, const float4 kw,
                                           const float4 k2, const float4 k3,
                                           const float4 k4) {
    const float t0 = xv.x + kw.x;
    const float t1 = xv.y + kw.y;
    const float t2 = xv.z + kw.z;
    const float t3 = xv.w + kw.w;
    const float S0 = __sinf(t0), C0 = __cosf(t0);
    const float S1 = __sinf(t1), C1 = __cosf(t1);
    const float S2 = __sinf(t2), C2 = __cosf(t2);
    const float S3 = __sinf(t3), C3 = __cosf(t3);

    const float C1C3 = C1 * C3;
    const float S1S3 = S1 * S3;
    const float C0C2 = C0 * C2;
    const float S0S2 = S0 * S2;
    const float C0S2 = C0 * S2;
    const float S0C2 = S0 * C2;

    // <Z0> = A0*C0C1C3 + B0*S0S1S3 + E0*C0S1S3 + F0*S0C1C3
    float o0 = k2.x * (C0 * C1C3);
    o0 = fmaf(k2.y, S0 * S1S3, o0);
    o0 = fmaf(k2.z, C0 * S1S3, o0);
    o0 = fmaf(k2.w, S0 * C1C3, o0);

    // <Z1> = A1*C0C2C3 + B1*S0S2C3
    float o1 = k3.x * (C0C2 * C3);
    o1 = fmaf(k3.y, S0S2 * C3, o1);

    // <Z2> = A2*C1C3 + B2*S1S3
    const float o2 = fmaf(k3.z, C1C3, k3.w * S1S3);

    // <Z3> = A3*C0C2 + B3*S0S2 + E3*C0S2 + F3*S0C2
    float o3 = k4.x * C0C2;
    o3 = fmaf(k4.y, S0S2, o3);
    o3 = fmaf(k4.z, C0S2, o3);
    o3 = fmaf(k4.w, S0C2, o3);

    float4 o;
    o.x = o0; o.y = o1; o.z = o2; o.w = o3;
    return o;
}

__global__ void __launch_bounds__(256)
qsim8_kernel(const float4* __restrict__ x4, const float4* __restrict__ w4,
             float4* __restrict__ out4) {
    const int b = blockIdx.x;          // 0..1023
    const int c = threadIdx.x;         // circuit

    // Batch all independent loads first (MLP).
    const float4 xv0 = x4[(b + 0 * NBQ) * NC + c];
    const float4 xv1 = x4[(b + 1 * NBQ) * NC + c];
    const float4 xv2 = x4[(b + 2 * NBQ) * NC + c];
    const float4 xv3 = x4[(b + 3 * NBQ) * NC + c];
    const float4 kw = w4[2 * c];        // w0 angles (layer 1)  -> merged into Theta
    const float4 w1 = w4[2 * c + 1];    // w1 angles (layer 2)

    // Analytic Heisenberg coefficients: products of full-angle cos/sin(w1_q).
    const float c0 = __cosf(w1.x), s0 = __sinf(w1.x);
    const float c1 = __cosf(w1.y), s1 = __sinf(w1.y);
    const float c2 = __cosf(w1.z), s2 = __sinf(w1.z);
    const float c3 = __cosf(w1.w), s3 = __sinf(w1.w);

    const float c1c2 = c1 * c2;
    const float s1s2 = s1 * s2;
    const float c2c3 = c2 * c3;
    const float s2s3 = s2 * s3;

    float4 k2, k3, k4;
    k2.x = c1c2 * c3;        // A0
    k2.y = c1c2 * s3;        // B0
    k2.z = s1s2 * c3;        // E0
    k2.w = s1s2 * s3;        // F0
    k3.x = c0 * c1;          // A1
    k3.y = s0 * s1;          // B1
    k3.z = c0 * c1c2;        // A2
    k3.w = c0 * s1s2;        // B2
    k4.x = k3.z * c3;        // A3 = c0c1c2c3
    k4.y = k3.y * c2c3;      // B3 = s0s1c2c3
    k4.z = (s0 * c1) * s2s3; // E3 = s0c1s2s3
    k4.w = k3.w * s3;        // F3 = c0s1s2s3

    const float4 o0 = eval_sim(xv0, kw, k2, k3, k4);
    const float4 o1 = eval_sim(xv1, kw, k2, k3, k4);
    const float4 o2 = eval_sim(xv2, kw, k2, k3, k4);
    const float4 o3 = eval_sim(xv3, kw, k2, k3, k4);

    out4[(b + 0 * NBQ) * NC + c] = o0;
    out4[(b + 1 * NBQ) * NC + c] = o1;
    out4[(b + 2 * NBQ) * NC + c] = o2;
    out4[(b + 3 * NBQ) * NC + c] = o3;
}

extern "C" void kernel_launch(void* const* d_in, const int* in_sizes, int n_in,
                              void* d_out, int out_size) {
    const float* x = (const float*)d_in[0];        // (4096, 1024)
    const float* w = (const float*)d_in[1];        // (256, 2, 4)
    float* out = (float*)d_out;                    // (4096, 1024)

    qsim8_kernel<<<NBQ, 256>>>(reinterpret_cast<const float4*>(x),
                               reinterpret_cast<const float4*>(w),
                               reinterpret_cast<float4*>(out));
}

// round 10
// speedup vs baseline: 1.2399x; 1.0295x over previous
#include <cuda_runtime.h>
#include <math.h>

#define NB 4096
#define NC 256
#define ROWS 8
#define NBQ (NB / ROWS)   // 512

// One full Heisenberg evaluation from an x-vector and register-resident coefs.
__device__ __forceinline__ float4 eval_sim(const float4 xv, const float4 kw,
                                           const float4 k2, const float4 k3,
                                           const float4 k4) {
    const float t0 = xv.x + kw.x;
    const float t1 = xv.y + kw.y;
    const float t2 = xv.z + kw.z;
    const float t3 = xv.w + kw.w;
    const float S0 = __sinf(t0), C0 = __cosf(t0);
    const float S1 = __sinf(t1), C1 = __cosf(t1);
    const float S2 = __sinf(t2), C2 = __cosf(t2);
    const float S3 = __sinf(t3), C3 = __cosf(t3);

    const float C1C3 = C1 * C3;
    const float S1S3 = S1 * S3;
    const float C0C2 = C0 * C2;
    const float S0S2 = S0 * S2;
    const float C0S2 = C0 * S2;
    const float S0C2 = S0 * C2;

    // <Z0> = A0*C0C1C3 + B0*S0S1S3 + E0*C0S1S3 + F0*S0C1C3
    float o0 = k2.x * (C0 * C1C3);
    o0 = fmaf(k2.y, S0 * S1S3, o0);
    o0 = fmaf(k2.z, C0 * S1S3, o0);
    o0 = fmaf(k2.w, S0 * C1C3, o0);

    // <Z1> = A1*C0C2C3 + B1*S0S2C3
    float o1 = k3.x * (C0C2 * C3);
    o1 = fmaf(k3.y, S0S2 * C3, o1);

    // <Z2> = A2*C1C3 + B2*S1S3
    const float o2 = fmaf(k3.z, C1C3, k3.w * S1S3);

    // <Z3> = A3*C0C2 + B3*S0S2 + E3*C0S2 + F3*S0C2
    float o3 = k4.x * C0C2;
    o3 = fmaf(k4.y, S0S2, o3);
    o3 = fmaf(k4.z, C0S2, o3);
    o3 = fmaf(k4.w, S0C2, o3);

    float4 o;
    o.x = o0; o.y = o1; o.z = o2; o.w = o3;
    return o;
}

__global__ void __launch_bounds__(256, 4)
qsim9_kernel(const float4* __restrict__ x4, const float4* __restrict__ w4,
             float4* __restrict__ out4) {
    const int b = blockIdx.x;          // 0..511
    const int c = threadIdx.x;         // circuit

    // Batch all independent loads first (MLP ~ 10).
    float4 xv[ROWS];
#pragma unroll
    for (int r = 0; r < ROWS; ++r)
        xv[r] = x4[(b + r * NBQ) * NC + c];
    const float4 kw = w4[2 * c];        // w0 angles (layer 1) -> merged into Theta
    const float4 w1 = w4[2 * c + 1];    // w1 angles (layer 2)

    // Analytic Heisenberg coefficients: products of full-angle cos/sin(w1_q).
    const float c0 = __cosf(w1.x), s0 = __sinf(w1.x);
    const float c1 = __cosf(w1.y), s1 = __sinf(w1.y);
    const float c2 = __cosf(w1.z), s2 = __sinf(w1.z);
    const float c3 = __cosf(w1.w), s3 = __sinf(w1.w);

    const float c1c2 = c1 * c2;
    const float s1s2 = s1 * s2;
    const float c2c3 = c2 * c3;
    const float s2s3 = s2 * s3;

    float4 k2, k3, k4;
    k2.x = c1c2 * c3;        // A0
    k2.y = c1c2 * s3;        // B0
    k2.z = s1s2 * c3;        // E0
    k2.w = s1s2 * s3;        // F0
    k3.x = c0 * c1;          // A1
    k3.y = s0 * s1;          // B1
    k3.z = c0 * c1c2;        // A2
    k3.w = c0 * s1s2;        // B2
    k4.x = k3.z * c3;        // A3 = c0c1c2c3
    k4.y = k3.y * c2c3;      // B3 = s0s1c2c3
    k4.z = (s0 * c1) * s2s3; // E3 = s0c1s2s3
    k4.w = k3.w * s3;        // F3 = c0s1s2s3

#pragma unroll
    for (int r = 0; r < ROWS; ++r) {
        const float4 o = eval_sim(xv[r], kw, k2, k3, k4);
        out4[(b + r * NBQ) * NC + c] = o;
    }
}

extern "C" void kernel_launch(void* const* d_in, const int* in_sizes, int n_in,
                              void* d_out, int out_size) {
    const float* x = (const float*)d_in[0];        // (4096, 1024)
    const float* w = (const float*)d_in[1];        // (256, 2, 4)
    float* out = (float*)d_out;                    // (4096, 1024)

    qsim9_kernel<<<NBQ, 256>>>(reinterpret_cast<const float4*>(x),
                               reinterpret_cast<const float4*>(w),
                               reinterpret_cast<float4*>(out));
}